// round 8
// baseline (speedup 1.0000x reference)
#include <cuda_runtime.h>
#include <cstdint>

#define BATCH 256
#define L 4096
#define H 128

// branchless elu
__device__ __forceinline__ float elu1(float x) {
    return fmaxf(x, 0.f) + (__expf(fminf(x, 0.f)) - 1.f);
}
// round f32 -> tf32 bit-pattern (still a valid f32)
__device__ __forceinline__ uint32_t tf32u(float x) {
    uint32_t u; asm("cvt.rna.tf32.f32 %0, %1;" : "=r"(u) : "f"(x)); return u;
}
__device__ __forceinline__ float tf32r(float x) {
    return __uint_as_float(tf32u(x));
}
// m16n8k8 tf32 MMA, D accumulate in-place
__device__ __forceinline__ void mma8(float& d0, float& d1, float& d2, float& d3,
                                     uint32_t a0, uint32_t a1, uint32_t a2, uint32_t a3,
                                     uint32_t b0, uint32_t b1)
{
    asm volatile("mma.sync.aligned.m16n8k8.row.col.f32.tf32.tf32.f32 "
                 "{%0,%1,%2,%3}, {%4,%5,%6,%7}, {%8,%9}, {%0,%1,%2,%3};"
                 : "+f"(d0), "+f"(d1), "+f"(d2), "+f"(d3)
                 : "r"(a0), "r"(a1), "r"(a2), "r"(a3), "r"(b0), "r"(b1));
}
// k-permutation so that B-fragment pair (k, k+4) sits at adjacent floats:
// pos(k) = (k & ~7) | ((k&3)<<1) | ((k>>2)&1)
__device__ __forceinline__ int posk(int k) {
    return (k & ~7) | ((k & 3) << 1) | ((k >> 2) & 1);
}

// One CTA = 2 batch elements, 256 threads = 8 warps.
// Warp w owns output rows {16w+g, 16w+g+8 : g=0..7} via m16n8k8 tf32 MMA:
//   A (stationary regs) = W_c columns;  B = h (2 batches in cols 0,1; cols 2-7 junk);
//   D accumulates over 16 k-tiles in-register (even/odd chains) — NO shfl reduction.
// h stored in SMEM k-PERMUTED and tf32-rounded so each k-tile's B fragment is one
// LDS.64. Layer-2's "+ h1_new" is warp-local (same rows). One __syncthreads/step.
// Output head amortized in a 32-slot ring, reduced every 16 steps (R4 scheme).
__global__ void __launch_bounds__(256, 1)
rnn_scan_kernel(const int* __restrict__ x,
                const float* __restrict__ W_in,
                const float* __restrict__ W_c,
                const float* __restrict__ W_out,
                const float* __restrict__ b_out,
                float* __restrict__ out)
{
    __shared__ __align__(16) float sh_h1[2][2 * H];     // [parity][b*H + pos(k)]
    __shared__ __align__(16) float sh_h2[2][2 * H];
    __shared__ __align__(16) float sh_r[3 * H];         // ORIGINAL index order
    __shared__ __align__(16) float sh_prod[32][2 * H];  // ring of h2*wout (perm order, sum-invariant)
    __shared__ uint8_t sh_x[2 * L];
    __shared__ float sh_acc[8][2];

    const int tid  = threadIdx.x;
    const int warp = tid >> 5;
    const int lane = tid & 31;
    const int lg   = lane >> 2;          // group id (0..7)
    const int lr   = lane & 3;           // thread-in-group
    const int b0   = blockIdx.x * 2;

    // ---- stage x; precompute r (orig order); zero parity-0 h ----
    const int* xg = x + (size_t)b0 * L;
    #pragma unroll 4
    for (int idx = tid; idx < 2 * L; idx += 256) sh_x[idx] = (uint8_t)xg[idx];
    if (tid < 2 * H) sh_r[tid] = elu1(W_in[tid]);
    if (tid < H)     sh_r[2 * H + tid] = 0.f;
    if (tid < 2 * H) { sh_h1[0][tid] = 0.f; sh_h2[0][tid] = 0.f; }

    // ---- A fragments (stationary): rows r0 = 16*warp+lg, r1 = r0+8 ----
    const int r0 = 16 * warp + lg;
    const int r1 = r0 + 8;
    uint32_t A1[16][4], A2[16][4];
    {
        const float* Wc0 = W_c;
        const float* Wc1 = W_c + H * H;
        #pragma unroll
        for (int c = 0; c < 16; ++c) {
            const int k0 = 8 * c + lr;
            A1[c][0] = tf32u(Wc0[(k0    ) * H + r0]);
            A1[c][1] = tf32u(Wc0[(k0    ) * H + r1]);
            A1[c][2] = tf32u(Wc0[(k0 + 4) * H + r0]);
            A1[c][3] = tf32u(Wc0[(k0 + 4) * H + r1]);
            A2[c][0] = tf32u(Wc1[(k0    ) * H + r0]);
            A2[c][1] = tf32u(Wc1[(k0    ) * H + r1]);
            A2[c][2] = tf32u(Wc1[(k0 + 4) * H + r0]);
            A2[c][3] = tf32u(Wc1[(k0 + 4) * H + r1]);
        }
    }
    const float w_r0 = W_out[r0];
    const float w_r1 = W_out[r1];
    const float bout = b_out[0];
    // B-fragment float offset for this lane: batch col = lg (cols 2-7 duplicate batches)
    const int boff = (lg & 1) * H + 2 * lr;
    // epilogue store positions (fixed per thread)
    const int pr0 = posk(r0);
    const int pr1 = posk(r1);
    const bool el = (lr == 0);

    float hacc0 = 0.f, hacc1 = 0.f;
    __syncthreads();

    for (int t = 0; t < L; ++t) {
        // ===== amortized head: window [t-16, t-1], 2 slots per warp, both batches
        if ((t & 15) == 0 && t > 0) {
            #pragma unroll
            for (int e = 0; e < 2; ++e) {
                const int u    = t - 16 + 2 * warp + e;
                const int slot = u & 31;
                #pragma unroll
                for (int b = 0; b < 2; ++b) {
                    const float4 v = *(const float4*)&sh_prod[slot][b * H + lane * 4];
                    float sr = (v.x + v.y) + (v.z + v.w);
                    #pragma unroll
                    for (int off = 16; off; off >>= 1)
                        sr += __shfl_xor_sync(0xffffffffu, sr, off);
                    const float logit = sr + bout;
                    const int   xt    = sh_x[b * L + u];
                    const float m     = fmaxf(logit, 0.f);
                    const float lse   = m + __logf(__expf(-m) + __expf(logit - m));
                    const float gv    = 0.5f * ((xt ? logit : 0.f) - lse);
                    if (b == 0) hacc0 += gv; else hacc1 += gv;
                }
            }
        }

        const int p = t & 1;
        const float* h1r = &sh_h1[p][0];
        const float* h2r = &sh_h2[p][0];
        float*       h1w = &sh_h1[p ^ 1][0];
        float*       h2w = &sh_h2[p ^ 1][0];

        const int prev0 = t ? (int)sh_x[t - 1]     : 2;
        const int prev1 = t ? (int)sh_x[L + t - 1] : 2;

        // ===== both layers' matvecs on the tensor pipe (4 indep chains) =====
        float D1e[4] = {0,0,0,0}, D1o[4] = {0,0,0,0};
        float D2e[4] = {0,0,0,0}, D2o[4] = {0,0,0,0};
        #pragma unroll
        for (int c = 0; c < 16; c += 2) {
            const float2 b1a = *(const float2*)(h1r + boff + 8 * c);
            const float2 b2a = *(const float2*)(h2r + boff + 8 * c);
            const float2 b1b = *(const float2*)(h1r + boff + 8 * c + 8);
            const float2 b2b = *(const float2*)(h2r + boff + 8 * c + 8);
            mma8(D1e[0], D1e[1], D1e[2], D1e[3],
                 A1[c][0], A1[c][1], A1[c][2], A1[c][3],
                 __float_as_uint(b1a.x), __float_as_uint(b1a.y));
            mma8(D2e[0], D2e[1], D2e[2], D2e[3],
                 A2[c][0], A2[c][1], A2[c][2], A2[c][3],
                 __float_as_uint(b2a.x), __float_as_uint(b2a.y));
            mma8(D1o[0], D1o[1], D1o[2], D1o[3],
                 A1[c+1][0], A1[c+1][1], A1[c+1][2], A1[c+1][3],
                 __float_as_uint(b1b.x), __float_as_uint(b1b.y));
            mma8(D2o[0], D2o[1], D2o[2], D2o[3],
                 A2[c+1][0], A2[c+1][1], A2[c+1][2], A2[c+1][3],
                 __float_as_uint(b2b.x), __float_as_uint(b2b.y));
        }

        // ===== epilogue: lanes lr==0 hold cols 0,1 = batches 0,1 =====
        if (el) {
            const float d10 = D1e[0] + D1o[0];   // (r0, b0)
            const float d11 = D1e[1] + D1o[1];   // (r0, b1)
            const float d12 = D1e[2] + D1o[2];   // (r1, b0)
            const float d13 = D1e[3] + D1o[3];   // (r1, b1)
            const float d20 = D2e[0] + D2o[0];
            const float d21 = D2e[1] + D2o[1];
            const float d22 = D2e[2] + D2o[2];
            const float d23 = D2e[3] + D2o[3];

            const float v00 = elu1(d10) + sh_r[prev0 * H + r0];
            const float v01 = elu1(d11) + sh_r[prev1 * H + r0];
            const float v10 = elu1(d12) + sh_r[prev0 * H + r1];
            const float v11 = elu1(d13) + sh_r[prev1 * H + r1];
            h1w[pr0]     = tf32r(v00);
            h1w[H + pr0] = tf32r(v01);
            h1w[pr1]     = tf32r(v10);
            h1w[H + pr1] = tf32r(v11);

            const float u00 = elu1(d20) + v00;
            const float u01 = elu1(d21) + v01;
            const float u10 = elu1(d22) + v10;
            const float u11 = elu1(d23) + v11;
            h2w[pr0]     = tf32r(u00);
            h2w[H + pr0] = tf32r(u01);
            h2w[pr1]     = tf32r(u10);
            h2w[H + pr1] = tf32r(u11);

            float* pr = &sh_prod[t & 31][0];
            pr[pr0]     = u00 * w_r0;
            pr[H + pr0] = u01 * w_r0;
            pr[pr1]     = u10 * w_r1;
            pr[H + pr1] = u11 * w_r1;
        }

        __syncthreads();   // single barrier per step
    }

    // ===== epilogue: reduce last 16 slots [L-16, L-1] =====
    #pragma unroll
    for (int e = 0; e < 2; ++e) {
        const int u    = L - 16 + 2 * warp + e;
        const int slot = u & 31;
        #pragma unroll
        for (int b = 0; b < 2; ++b) {
            const float4 v = *(const float4*)&sh_prod[slot][b * H + lane * 4];
            float sr = (v.x + v.y) + (v.z + v.w);
            #pragma unroll
            for (int off = 16; off; off >>= 1)
                sr += __shfl_xor_sync(0xffffffffu, sr, off);
            const float logit = sr + bout;
            const int   xt    = sh_x[b * L + u];
            const float m     = fmaxf(logit, 0.f);
            const float lse   = m + __logf(__expf(-m) + __expf(logit - m));
            const float gv    = 0.5f * ((xt ? logit : 0.f) - lse);
            if (b == 0) hacc0 += gv; else hacc1 += gv;
        }
    }

    if (lane == 0) { sh_acc[warp][0] = hacc0; sh_acc[warp][1] = hacc1; }
    __syncthreads();
    if (tid < 2) {
        float a = 0.f;
        #pragma unroll
        for (int w = 0; w < 8; ++w) a += sh_acc[w][tid];
        out[b0 + tid] = a;
    }
}

extern "C" void kernel_launch(void* const* d_in, const int* in_sizes, int n_in,
                              void* d_out, int out_size)
{
    const int*   x     = (const int*)  d_in[0];
    const float* W_in  = (const float*)d_in[1];
    const float* W_c   = (const float*)d_in[2];
    const float* W_out = (const float*)d_in[3];
    const float* b_out = (const float*)d_in[4];

    rnn_scan_kernel<<<BATCH / 2, 256>>>(x, W_in, W_c, W_out, b_out, (float*)d_out);
}